// round 2
// baseline (speedup 1.0000x reference)
#include <cuda_runtime.h>

// LRN, all-ones cross-channel 5x5 filter:
//   s[b,h,w] = sum_c x[b,c,h,w]^2
//   y        = 5x5 zero-padded box filter of s
//   out      = x * (2 + 1e-4*y)^(-0.75)
//
// SMEM-resident fused kernel: one block per (batch, 16x32 spatial tile).
// Phase 1: stream 96 channels over the 20x36 halo tile ONCE; accumulate
//          channel-sum-of-squares in registers; park interior x in SMEM (192KB).
// Phase 2: 5x5 box filter + fast pow in SMEM.
// Phase 3: scale from SMEM (no gmem re-read), float4 stores.

#define Bn 16
#define Cn 96
#define Hn 224
#define Wn 224
#define HWn (Hn * Wn)            // 50176
#define TW 32
#define TH 16
#define NPIX (TW * TH)           // 512 interior pixels
#define SW (TW + 4)              // 36
#define SH (TH + 4)              // 20
#define NPOS (SW * SH)           // 720 halo positions
#define NTHREADS 768
#define SMEM_BYTES ((Cn * NPIX + NPOS + NPIX) * 4)   // 196608 + 2880 + 2048 = 201536

__global__ __launch_bounds__(NTHREADS, 1)
void lrn_fused_kernel(const float* __restrict__ x, float* __restrict__ out) {
    extern __shared__ float smem[];
    float* x_s = smem;                      // [96][512] interior x values
    float* s_s = smem + Cn * NPIX;          // [720] channel-summed squares (halo tile)
    float* f_s = s_s + NPOS;                // [512] per-pixel scale factor

    const int tid = threadIdx.x;
    const int b  = blockIdx.z;
    const int h0 = blockIdx.y * TH;
    const int w0 = blockIdx.x * TW;
    const int img = b * Cn * HWn;           // max 77M, fits int32

    // ---------------- Phase 1: stream channels once ---------------------------
    if (tid < NPOS) {
        const int i  = tid / SW;
        const int j  = tid - i * SW;
        const int gh = h0 - 2 + i;
        const int gw = w0 - 2 + j;
        const bool valid = ((unsigned)gh < (unsigned)Hn) & ((unsigned)gw < (unsigned)Wn);
        const bool interior = (i >= 2) & (i < 2 + TH) & (j >= 2) & (j < 2 + TW);
        const int sidx = (i - 2) * TW + (j - 2);
        const float* px = x + img + gh * Wn + gw;   // only deref'd when valid

        float acc = 0.0f;
#pragma unroll 8
        for (int c = 0; c < Cn; c++) {
            float v = valid ? __ldg(px + c * HWn) : 0.0f;
            acc = fmaf(v, v, acc);
            if (interior) x_s[c * NPIX + sidx] = v;
        }
        s_s[tid] = acc;
    }
    __syncthreads();

    // ---------------- Phase 2: 5x5 box filter + pow(-0.75) --------------------
    if (tid < NPIX) {
        const int i = tid >> 5;        // row in 16x32 tile
        const int j = tid & 31;
        float sum = 0.0f;
#pragma unroll
        for (int di = 0; di < 5; di++) {
#pragma unroll
            for (int dj = 0; dj < 5; dj++) {
                sum += s_s[(i + di) * SW + (j + dj)];
            }
        }
        const float bse = fmaf(1e-4f, sum, 2.0f);   // >= 2, safe for fast log
        f_s[tid] = __powf(bse, -0.75f);
    }
    __syncthreads();

    // ---------------- Phase 3: out = x * f from SMEM, float4 stores -----------
    const float4* x4 = (const float4*)x_s;          // [96][128] quads
    const float4* f4 = (const float4*)f_s;          // [128] quads
    float4* o4 = (float4*)out;
    const int obase = (img >> 2) + h0 * (Wn >> 2) + (w0 >> 2);
    const int stride4 = HWn >> 2;                   // 12544

#pragma unroll
    for (int k = 0; k < (Cn * NPIX / 4) / NTHREADS; k++) {   // 16 iterations
        const int idx = tid + k * NTHREADS;
        const int c  = idx >> 7;       // quad-channel (128 quads per channel)
        const int q  = idx & 127;
        const int r  = q >> 3;         // row in tile
        const int qw = q & 7;          // quad within row
        float4 v = x4[(c << 7) + q];
        const float4 f = f4[q];
        v.x *= f.x; v.y *= f.y; v.z *= f.z; v.w *= f.w;
        o4[obase + c * stride4 + r * (Wn >> 2) + qw] = v;
    }
}

extern "C" void kernel_launch(void* const* d_in, const int* in_sizes, int n_in,
                              void* d_out, int out_size) {
    const float* x = (const float*)d_in[0];
    float* out = (float*)d_out;
    cudaFuncSetAttribute(lrn_fused_kernel,
                         cudaFuncAttributeMaxDynamicSharedMemorySize, SMEM_BYTES);
    dim3 grid(Wn / TW, Hn / TH, Bn);   // 7 x 14 x 16 = 1568 blocks
    lrn_fused_kernel<<<grid, NTHREADS, SMEM_BYTES>>>(x, out);
}